// round 12
// baseline (speedup 1.0000x reference)
#include <cuda_runtime.h>
#include <cuda_bf16.h>
#include <cstdint>
#include <math.h>

#define T_SEQ 2048
#define D_EMB 4096
#define QKV_N 6144
#define NH 32
#define DH 128
#define NG 8

// ---------------------------------------------------------------------------
// Scratch (__device__ globals; no cudaMalloc allowed)
// ---------------------------------------------------------------------------
__device__ float g_qkv[T_SEQ * QKV_N];              // fp32 QKV (gemm1 out)
__device__ __nv_bfloat16 g_qkvh[T_SEQ * QKV_N];     // roped+split QKV hi
__device__ __nv_bfloat16 g_qkvl[T_SEQ * QKV_N];     // roped+split QKV lo
__device__ float g_xp[T_SEQ * D_EMB];               // x  prepped (tf32+perm)
__device__ float g_yp[T_SEQ * D_EMB];               // y  prepped (tf32+perm)
__device__ float g_wqp[QKV_N * D_EMB];              // Wqkv prepped
__device__ float g_wop[D_EMB * D_EMB];              // Wout prepped

// ---------------------------------------------------------------------------
// helpers
// ---------------------------------------------------------------------------
__device__ __forceinline__ uint32_t smem_u32(const void* p) {
    uint32_t a;
    asm("{ .reg .u64 t; cvta.to.shared.u64 t, %1; cvt.u32.u64 %0, t; }"
        : "=r"(a) : "l"(p));
    return a;
}
__device__ __forceinline__ void cp_async16(uint32_t dst, const void* src) {
    asm volatile("cp.async.cg.shared.global [%0], [%1], 16;"
                 :: "r"(dst), "l"(src));
}
__device__ __forceinline__ void cp_commit() {
    asm volatile("cp.async.commit_group;");
}
template <int N>
__device__ __forceinline__ void cp_wait() {
    asm volatile("cp.async.wait_group %0;" :: "n"(N));
}
__device__ __forceinline__ void ldsm_x4(uint32_t* r, uint32_t addr) {
    asm volatile("ldmatrix.sync.aligned.m8n8.x4.shared.b16 {%0,%1,%2,%3}, [%4];"
                 : "=r"(r[0]), "=r"(r[1]), "=r"(r[2]), "=r"(r[3]) : "r"(addr));
}
__device__ __forceinline__ void ldsm_x4_t(uint32_t* r, uint32_t addr) {
    asm volatile(
        "ldmatrix.sync.aligned.m8n8.x4.trans.shared.b16 {%0,%1,%2,%3}, [%4];"
        : "=r"(r[0]), "=r"(r[1]), "=r"(r[2]), "=r"(r[3]) : "r"(addr));
}
__device__ __forceinline__ void mma_bf16(float* d, const uint32_t* a,
                                         uint32_t b0, uint32_t b1) {
    asm volatile(
        "mma.sync.aligned.m16n8k16.row.col.f32.bf16.bf16.f32 "
        "{%0,%1,%2,%3}, {%4,%5,%6,%7}, {%8,%9}, {%0,%1,%2,%3};"
        : "+f"(d[0]), "+f"(d[1]), "+f"(d[2]), "+f"(d[3])
        : "r"(a[0]), "r"(a[1]), "r"(a[2]), "r"(a[3]), "r"(b0), "r"(b1));
}
__device__ __forceinline__ void mma_tf32(float* d, const uint32_t* a,
                                         uint32_t b0, uint32_t b1) {
    asm volatile(
        "mma.sync.aligned.m16n8k8.row.col.f32.tf32.tf32.f32 "
        "{%0,%1,%2,%3}, {%4,%5,%6,%7}, {%8,%9}, {%0,%1,%2,%3};"
        : "+f"(d[0]), "+f"(d[1]), "+f"(d[2]), "+f"(d[3])
        : "r"(a[0]), "r"(a[1]), "r"(a[2]), "r"(a[3]), "r"(b0), "r"(b1));
}
__device__ __forceinline__ uint32_t cvt_tf32(float x) {
    uint32_t r;
    asm("cvt.rna.tf32.f32 %0, %1;" : "=r"(r) : "f"(x));
    return r;
}

// fast exp: 2^(x*log2e) via round+poly, FMA-only (no MUFU).
__device__ __forceinline__ float fexp(float x) {
    x = fmaxf(x, -88.0f);
    float t  = fmaf(x, 1.4426950408889634f, 12582912.0f);
    float nf = t - 12582912.0f;
    float r  = fmaf(x, 1.4426950408889634f, -nf);
    float p  = 1.3333558146428443e-3f;
    p = fmaf(p, r, 9.6181291076284772e-3f);
    p = fmaf(p, r, 5.5504108664821580e-2f);
    p = fmaf(p, r, 2.4022650695910072e-1f);
    p = fmaf(p, r, 6.9314718055994531e-1f);
    p = fmaf(p, r, 1.0f);
    int n = (int)nf;
    return p * __int_as_float((n + 127) << 23);
}

// split pair of fp32 -> packed bf16x2 hi and lo
__device__ __forceinline__ void split2(float a, float b,
                                       uint32_t& hi, uint32_t& lo) {
    __nv_bfloat16 ha = __float2bfloat16(a), hb = __float2bfloat16(b);
    float ra = a - __bfloat162float(ha);
    float rb = b - __bfloat162float(hb);
    __nv_bfloat162 H = __halves2bfloat162(ha, hb);
    __nv_bfloat162 L = __halves2bfloat162(__float2bfloat16(ra),
                                          __float2bfloat16(rb));
    hi = *(uint32_t*)&H;
    lo = *(uint32_t*)&L;
}

// ---------------------------------------------------------------------------
// Prep: fp32 -> tf32-rounded bits, K-columns permuted within each 8-group
// to order [0,4,1,5,2,6,3,7].
// ---------------------------------------------------------------------------
__global__ void prep_tf32_kernel(const float* __restrict__ in,
                                 float* __restrict__ out, int ngroups) {
    int gidx = blockIdx.x * blockDim.x + threadIdx.x;
    if (gidx >= ngroups) return;
    size_t base = (size_t)gidx * 8;
    float4 lo = *(const float4*)(in + base);
    float4 hi = *(const float4*)(in + base + 4);
    float4 o0, o1;
    o0.x = __uint_as_float(cvt_tf32(lo.x));
    o0.y = __uint_as_float(cvt_tf32(hi.x));
    o0.z = __uint_as_float(cvt_tf32(lo.y));
    o0.w = __uint_as_float(cvt_tf32(hi.y));
    o1.x = __uint_as_float(cvt_tf32(lo.z));
    o1.y = __uint_as_float(cvt_tf32(hi.z));
    o1.z = __uint_as_float(cvt_tf32(lo.w));
    o1.w = __uint_as_float(cvt_tf32(hi.w));
    *(float4*)(out + base) = o0;
    *(float4*)(out + base + 4) = o1;
}

// ---------------------------------------------------------------------------
// tf32 GEMM on prepped operands. CTA 128x128, BK=32, 128 threads = 4 warps
// (2m x 2n), warp tile 64x64 -> 128 B smem read per MMA (crossbar-relieved).
// 2 CTAs/SM, 2-stage cp.async.
// ---------------------------------------------------------------------------
#define P2 160
#define A2 (128 * P2)                 // 20480 per tensor
#define S2 (2 * A2)                   // 40960 per stage
#define GEMM_SMEM (2 * S2)            // 81920

__device__ __forceinline__ void tf32_stage_load(
    uint32_t stg, const float* A, const float* B, int K, int k0, int tid)
{
#pragma unroll
    for (int i = 0; i < 16; i++) {
        int c = tid + i * 128;                 // 0..2047 16B chunks
        int sel = c >> 10;                     // 0=A, 1=B
        int rem = c & 1023;
        int row = rem >> 3, ch = rem & 7;
        const float* src = sel ? B : A;
        cp_async16(stg + sel * A2 + row * P2 + ch * 16,
                   src + (size_t)row * K + k0 + ch * 4);
    }
}

__global__ __launch_bounds__(128, 2) void gemm_tf32p(
    const float* __restrict__ A, const float* __restrict__ B,
    float* __restrict__ C, int M, int N, int K)
{
    extern __shared__ __align__(128) char sm[];
    const uint32_t sbase = smem_u32(sm);

    const int tid = threadIdx.x;
    const int wid = tid >> 5, lane = tid & 31;
    const int wm = wid >> 1, wn = wid & 1;         // 2m x 2n warps
    const int bm = blockIdx.x * 128, bn = blockIdx.y * 128;

    const float* Ab = A + (size_t)bm * K;
    const float* Bb = B + (size_t)bn * K;

    float acc[4][8][4];                            // 64m x 64n per warp
#pragma unroll
    for (int mt = 0; mt < 4; mt++)
#pragma unroll
        for (int nt = 0; nt < 8; nt++)
#pragma unroll
            for (int q = 0; q < 4; q++) acc[mt][nt][q] = 0.0f;

    const int nkt = K >> 5;

    tf32_stage_load(sbase,      Ab, Bb, K, 0,  tid); cp_commit();
    tf32_stage_load(sbase + S2, Ab, Bb, K, 32, tid); cp_commit();

    const int g = lane >> 2, c = lane & 3;
    const int arow = wm * 64 + g;
    const int brow = wn * 64 + g;

    for (int kt = 0; kt < nkt; kt++) {
        cp_wait<1>();
        __syncthreads();
        const uint32_t stgo = (kt & 1) * S2;

#pragma unroll
        for (int ks = 0; ks < 4; ks++) {
            const int kb = ks * 32 + c * 8;        // byte offset of k-pair
            uint32_t bf[8][2];
#pragma unroll
            for (int nt = 0; nt < 8; nt++) {
                uint2 v = *(const uint2*)(sm + stgo + A2
                                          + (brow + nt * 8) * P2 + kb);
                bf[nt][0] = v.x;
                bf[nt][1] = v.y;
            }
            uint32_t af[4][4];
#pragma unroll
            for (int mt = 0; mt < 4; mt++) {
                uint32_t ad = stgo + (arow + mt * 16) * P2 + kb;
                uint2 v0 = *(const uint2*)(sm + ad);
                uint2 v1 = *(const uint2*)(sm + ad + 8 * P2);
                af[mt][0] = v0.x; af[mt][2] = v0.y;
                af[mt][1] = v1.x; af[mt][3] = v1.y;
            }
#pragma unroll
            for (int mt = 0; mt < 4; mt++)
#pragma unroll
                for (int nt = 0; nt < 8; nt++)
                    mma_tf32(acc[mt][nt], af[mt], bf[nt][0], bf[nt][1]);
        }

        __syncthreads();
        if (kt + 2 < nkt) {
            tf32_stage_load(sbase + stgo, Ab, Bb, K, (kt + 2) * 32, tid);
        }
        cp_commit();
    }

    // epilogue
    const int l4 = lane & 3;
#pragma unroll
    for (int mt = 0; mt < 4; mt++) {
        const int r0 = bm + wm * 64 + mt * 16 + g;
#pragma unroll
        for (int nt = 0; nt < 8; nt++) {
            const int col = bn + wn * 64 + nt * 8 + l4 * 2;
            *(float2*)(C + (size_t)r0 * N + col) =
                make_float2(acc[mt][nt][0], acc[mt][nt][1]);
            *(float2*)(C + (size_t)(r0 + 8) * N + col) =
                make_float2(acc[mt][nt][2], acc[mt][nt][3]);
        }
    }
}

// ---------------------------------------------------------------------------
// Fused RoPE + bf16 hi/lo split of the QKV tensor (unchanged, passing).
// ---------------------------------------------------------------------------
__global__ void rope_split_kernel(const float* __restrict__ cosp,
                                  const float* __restrict__ sinp)
{
    int idx = blockIdx.x * blockDim.x + threadIdx.x;
    const int total = T_SEQ * NG * 6 * 64;
    if (idx >= total) return;
    int i = idx & 63;
    int r = idx >> 6;
    int s = r % 6; r /= 6;
    int g = r & 7;
    int t = r >> 3;

    const size_t off = (size_t)t * QKV_N + g * 768 + s * 128;
    const float* base = g_qkv + off;
    const float sc = (s < 4) ? 0.08838834764831845f : 1.0f;

    int d1, d2;
    float o1, o2;
    if (s < 5 && i < 32) {
        float x1 = base[i], x2 = base[i + 32];
        float c1 = cosp[t * 64 + i],      s1 = sinp[t * 64 + i];
        float c2 = cosp[t * 64 + i + 32], s2 = sinp[t * 64 + i + 32];
        o1 = (x1 * c1 - x2 * s1) * sc;
        o2 = (x2 * c2 + x1 * s2) * sc;
        d1 = i; d2 = i + 32;
    } else if (s < 5) {
        d1 = i + 32; d2 = i + 64;
        o1 = base[d1] * sc; o2 = base[d2] * sc;
    } else {
        d1 = i; d2 = i + 64;
        o1 = base[d1]; o2 = base[d2];
    }
    __nv_bfloat16 h1 = __float2bfloat16(o1);
    __nv_bfloat16 h2 = __float2bfloat16(o2);
    g_qkvh[off + d1] = h1;
    g_qkvh[off + d2] = h2;
    g_qkvl[off + d1] = __float2bfloat16(o1 - __bfloat162float(h1));
    g_qkvl[off + d2] = __float2bfloat16(o2 - __bfloat162float(h2));
}

// ---------------------------------------------------------------------------
// Tensor-core flash attention (bf16x3, causal) — unchanged from Round 11.
// q-block 64, kv-tile 32, 128 threads (4 warps), 2 CTAs/SM.
// ---------------------------------------------------------------------------
#define AP   272
#define KVT  (32 * AP)               // 8704 per tensor tile
#define KVBUF (4 * KVT)              // 34816 (Kh,Kl,Vh,Vl)
#define ATTN_SMEM (2 * KVBUF)        // 69632

__device__ __forceinline__ void attn_load_kv(
    uint32_t dstbase, const __nv_bfloat16* kh, const __nv_bfloat16* kl,
    const __nv_bfloat16* vh, const __nv_bfloat16* vl, int k0, int tid)
{
    const __nv_bfloat16* srcs[4] = {kh, kl, vh, vl};
#pragma unroll
    for (int it = 0; it < 16; it++) {
        int c = tid + it * 128;            // 0..2047 16B chunks
        int tensor = c >> 9;               // 512 chunks per tensor (32x16)
        int rem = c & 511;
        int row = rem >> 4, ch = rem & 15;
        cp_async16(dstbase + tensor * KVT + row * AP + ch * 16,
                   srcs[tensor] + (size_t)(k0 + row) * QKV_N + ch * 8);
    }
}

__global__ __launch_bounds__(128, 2) void attn_mma_kernel()
{
    extern __shared__ __align__(128) char sma[];
    const uint32_t sbase = smem_u32(sma);
    const int tid = threadIdx.x;
    const int wid = tid >> 5, lane = tid & 31;

    const int qb = (gridDim.x - 1) - blockIdx.x;   // 64-row q block, heavy first
    const int h  = blockIdx.y;
    const int g = h >> 2, s = h & 3;

    const __nv_bfloat16* Qh = g_qkvh + (size_t)(qb * 64) * QKV_N
                            + g * 768 + s * 128;
    const __nv_bfloat16* Ql = g_qkvl + (size_t)(qb * 64) * QKV_N
                            + g * 768 + s * 128;
    const __nv_bfloat16* Kh = g_qkvh + g * 768 + 512;
    const __nv_bfloat16* Kl = g_qkvl + g * 768 + 512;
    const __nv_bfloat16* Vh = g_qkvh + g * 768 + 640;
    const __nv_bfloat16* Vl = g_qkvl + g * 768 + 640;

    // ---- stage Q (64 rows x 128 dims, hi+lo) into smem, then registers ----
#pragma unroll
    for (int it = 0; it < 16; it++) {
        int c = tid + it * 128;            // 0..2047 chunks
        int tensor = c >> 10;              // 1024 chunks per tensor (64x16)
        int rem = c & 1023;
        int row = rem >> 4, ch = rem & 15;
        const __nv_bfloat16* src = (tensor ? Ql : Qh);
        cp_async16(sbase + tensor * (64 * AP) + row * AP + ch * 16,
                   src + (size_t)row * QKV_N + ch * 8);
    }
    cp_commit();
    cp_wait<0>();
    __syncthreads();

    uint32_t qfh[8][4], qfl[8][4];
    {
        uint32_t qa = sbase + (wid * 16 + (lane & 15)) * AP + (lane >> 4) * 16;
#pragma unroll
        for (int ks = 0; ks < 8; ks++) {
            ldsm_x4(qfh[ks], qa + ks * 32);
            ldsm_x4(qfl[ks], qa + 64 * AP + ks * 32);
        }
    }
    __syncthreads();

    const int nt_tiles = 2 * qb + 2;       // kv tiles of 32 covering (qb+1)*64
    attn_load_kv(sbase, Kh, Kl, Vh, Vl, 0, tid);
    cp_commit();
    attn_load_kv(sbase + KVBUF, Kh, Kl, Vh, Vl, 32, tid);
    cp_commit();

    float oacc[16][4];
#pragma unroll
    for (int nt = 0; nt < 16; nt++)
#pragma unroll
        for (int q = 0; q < 4; q++) oacc[nt][q] = 0.0f;
    float m0 = -1e30f, m1 = -1e30f, l0 = 0.0f, l1 = 0.0f;

    const int row0 = qb * 64 + wid * 16 + (lane >> 2);
    const int row1 = row0 + 8;

    for (int kt = 0; kt < nt_tiles; kt++) {
        cp_wait<1>();
        __syncthreads();
        const uint32_t kb = sbase + (kt & 1) * KVBUF;
        const int k0 = kt * 32;

        // ---- S = Q K^T (bf16x3), S tile 16x32 per warp ----
        float sacc[4][4];
#pragma unroll
        for (int nt = 0; nt < 4; nt++)
#pragma unroll
            for (int q = 0; q < 4; q++) sacc[nt][q] = 0.0f;

        const uint32_t kaddr = kb + (lane & 15) * AP + (lane >> 4) * 16;
#pragma unroll
        for (int ks = 0; ks < 8; ks++) {
#pragma unroll
            for (int p = 0; p < 2; p++) {
                uint32_t kh4[4], kl4[4];
                uint32_t a = kaddr + p * 16 * AP + ks * 32;
                ldsm_x4(kh4, a);
                ldsm_x4(kl4, a + KVT);
                mma_bf16(sacc[2 * p],     qfh[ks], kh4[0], kh4[2]);
                mma_bf16(sacc[2 * p],     qfh[ks], kl4[0], kl4[2]);
                mma_bf16(sacc[2 * p],     qfl[ks], kh4[0], kh4[2]);
                mma_bf16(sacc[2 * p + 1], qfh[ks], kh4[1], kh4[3]);
                mma_bf16(sacc[2 * p + 1], qfh[ks], kl4[1], kl4[3]);
                mma_bf16(sacc[2 * p + 1], qfl[ks], kh4[1], kh4[3]);
            }
        }

        // ---- causal mask ----
        if (k0 + 31 > row0) {
#pragma unroll
            for (int nt = 0; nt < 4; nt++) {
                int col = k0 + nt * 8 + 2 * (lane & 3);
                if (col     > row0) sacc[nt][0] = -1e30f;
                if (col + 1 > row0) sacc[nt][1] = -1e30f;
                if (col     > row1) sacc[nt][2] = -1e30f;
                if (col + 1 > row1) sacc[nt][3] = -1e30f;
            }
        }

        // ---- online softmax ----
        float mt0 = -1e30f, mt1 = -1e30f;
#pragma unroll
        for (int nt = 0; nt < 4; nt++) {
            mt0 = fmaxf(mt0, fmaxf(sacc[nt][0], sacc[nt][1]));
            mt1 = fmaxf(mt1, fmaxf(sacc[nt][2], sacc[nt][3]));
        }
        mt0 = fmaxf(mt0, __shfl_xor_sync(0xffffffffu, mt0, 1));
        mt0 = fmaxf(mt0, __shfl_xor_sync(0xffffffffu, mt0, 2));
        mt1 = fmaxf(mt1, __shfl_xor_sync(0xffffffffu, mt1, 1));
        mt1 = fmaxf(mt1, __shfl_xor_sync(0xffffffffu, mt1, 2));

        float mn0 = fmaxf(m0, mt0), mn1 = fmaxf(m1, mt1);
        float c0 = fexp(m0 - mn0), c1 = fexp(m1 - mn1);
        m0 = mn0; m1 = mn1;

        float s0 = 0.0f, s1 = 0.0f;
#pragma unroll
        for (int nt = 0; nt < 4; nt++) {
            sacc[nt][0] = fexp(sacc[nt][0] - m0);
            sacc[nt][1] = fexp(sacc[nt][1] - m0);
            sacc[nt][2] = fexp(sacc[nt][2] - m1);
            sacc[nt][3] = fexp(sacc[nt][3] - m1);
            s0 += sacc[nt][0] + sacc[nt][1];
            s1 += sacc[nt][2] + sacc[nt][3];
        }
        s0 += __shfl_xor_sync(0xffffffffu, s0, 1);
        s0 += __shfl_xor_sync(0xffffffffu, s0, 2);
        s1 += __shfl_xor_sync(0xffffffffu, s1, 1);
        s1 += __shfl_xor_sync(0xffffffffu, s1, 2);
        l0 = l0 * c0 + s0;
        l1 = l1 * c1 + s1;
#pragma unroll
        for (int nt = 0; nt < 16; nt++) {
            oacc[nt][0] *= c0; oacc[nt][1] *= c0;
            oacc[nt][2] *= c1; oacc[nt][3] *= c1;
        }

        // ---- O += P V (bf16x3); P fragments from registers ----
        const uint32_t vbase = kb + 2 * KVT
            + ((lane & 7) + ((lane >> 3) & 1) * 8) * AP + (lane >> 4) * 16;
#pragma unroll
        for (int kk = 0; kk < 2; kk++) {
            uint32_t pah[4], pal[4];
            split2(sacc[2 * kk][0],     sacc[2 * kk][1],     pah[0], pal[0]);
            split2(sacc[2 * kk][2],     sacc[2 * kk][3],     pah[1], pal[1]);
            split2(sacc[2 * kk + 1][0], sacc[2 * kk + 1][1], pah[2], pal[2]);
            split2(sacc[2 * kk + 1][2], sacc[2 * kk + 1][3], pah[3], pal[3]);
#pragma unroll
            for (int nb = 0; nb < 8; nb++) {
                uint32_t vh4[4], vl4[4];
                uint32_t va = vbase + kk * 16 * AP + nb * 32;
                ldsm_x4_t(vh4, va);
                ldsm_x4_t(vl4, va + KVT);
                mma_bf16(oacc[2 * nb],     pah, vh4[0], vh4[1]);
                mma_bf16(oacc[2 * nb],     pah, vl4[0], vl4[1]);
                mma_bf16(oacc[2 * nb],     pal, vh4[0], vh4[1]);
                mma_bf16(oacc[2 * nb + 1], pah, vh4[2], vh4[3]);
                mma_bf16(oacc[2 * nb + 1], pah, vl4[2], vl4[3]);
                mma_bf16(oacc[2 * nb + 1], pal, vh4[2], vh4[3]);
            }
        }

        __syncthreads();
        if (kt + 2 < nt_tiles)
            attn_load_kv(sbase + (kt & 1) * KVBUF, Kh, Kl, Vh, Vl,
                         (kt + 2) * 32, tid);
        cp_commit();
    }

    // epilogue: y = O / l, tf32-rounded + column-permuted into g_yp.
    const float il0 = 1.0f / l0, il1 = 1.0f / l1;
    const int l4 = lane & 3;
    const int p1 = (l4 < 2) ? 4 * l4 : 4 * l4 - 7;
    const int p2 = (l4 < 2) ? 4 * l4 + 2 : 4 * l4 - 5;
#pragma unroll
    for (int nt = 0; nt < 16; nt++) {
        size_t b0 = (size_t)row0 * D_EMB + h * DH + nt * 8;
        size_t b1 = (size_t)row1 * D_EMB + h * DH + nt * 8;
        g_yp[b0 + p1] = __uint_as_float(cvt_tf32(oacc[nt][0] * il0));
        g_yp[b0 + p2] = __uint_as_float(cvt_tf32(oacc[nt][1] * il0));
        g_yp[b1 + p1] = __uint_as_float(cvt_tf32(oacc[nt][2] * il1));
        g_yp[b1 + p2] = __uint_as_float(cvt_tf32(oacc[nt][3] * il1));
    }
}

// ---------------------------------------------------------------------------
// kernel_launch
// ---------------------------------------------------------------------------
extern "C" void kernel_launch(void* const* d_in, const int* in_sizes, int n_in,
                              void* d_out, int out_size)
{
    const float* x    = (const float*)d_in[0];
    const float* Wqkv = (const float*)d_in[1];
    const float* Wout = (const float*)d_in[2];
    const float* cosp = (const float*)d_in[3];
    const float* sinp = (const float*)d_in[4];
    float* out = (float*)d_out;

    float *qkv, *xp, *yp, *wqp, *wop;
    cudaGetSymbolAddress((void**)&qkv, g_qkv);
    cudaGetSymbolAddress((void**)&xp,  g_xp);
    cudaGetSymbolAddress((void**)&yp,  g_yp);
    cudaGetSymbolAddress((void**)&wqp, g_wqp);
    cudaGetSymbolAddress((void**)&wop, g_wop);

    cudaFuncSetAttribute(gemm_tf32p,
                         cudaFuncAttributeMaxDynamicSharedMemorySize,
                         GEMM_SMEM);
    cudaFuncSetAttribute(attn_mma_kernel,
                         cudaFuncAttributeMaxDynamicSharedMemorySize,
                         ATTN_SMEM);

    // 1) prep x, Wqkv, Wout (tf32 round + column permutation)
    {
        int gx = (T_SEQ * D_EMB) / 8;
        prep_tf32_kernel<<<(gx + 255) / 256, 256>>>(x, xp, gx);
        int gq = (QKV_N * D_EMB) / 8;
        prep_tf32_kernel<<<(gq + 255) / 256, 256>>>(Wqkv, wqp, gq);
        int go = (D_EMB * D_EMB) / 8;
        prep_tf32_kernel<<<(go + 255) / 256, 256>>>(Wout, wop, go);
    }
    // 2) QKV projection (tf32 tensor cores): qkv = x @ Wqkv^T
    gemm_tf32p<<<dim3(T_SEQ / 128, QKV_N / 128), 128, GEMM_SMEM>>>(
        xp, wqp, qkv, T_SEQ, QKV_N, D_EMB);
    // 3) fused RoPE + bf16 hi/lo split
    {
        int total = T_SEQ * NG * 6 * 64;
        rope_split_kernel<<<(total + 255) / 256, 256>>>(cosp, sinp);
    }
    // 4) tensor-core flash attention -> prepped y (g_yp)
    attn_mma_kernel<<<dim3(T_SEQ / 64, NH), 128, ATTN_SMEM>>>();
    // 5) output projection (tf32): out = y @ Wout^T
    gemm_tf32p<<<dim3(T_SEQ / 128, D_EMB / 128), 128, GEMM_SMEM>>>(
        yp, wop, out, T_SEQ, D_EMB, D_EMB);
}

// round 13
// speedup vs baseline: 1.0232x; 1.0232x over previous
#include <cuda_runtime.h>
#include <cuda_bf16.h>
#include <cstdint>
#include <math.h>

#define T_SEQ 2048
#define D_EMB 4096
#define QKV_N 6144
#define NH 32
#define DH 128
#define NG 8

// ---------------------------------------------------------------------------
// Scratch (__device__ globals; no cudaMalloc allowed)
// ---------------------------------------------------------------------------
__device__ float g_qkv[T_SEQ * QKV_N];              // fp32 QKV (gemm1 out)
__device__ __nv_bfloat16 g_qkvh[T_SEQ * QKV_N];     // roped+split QKV hi
__device__ __nv_bfloat16 g_qkvl[T_SEQ * QKV_N];     // roped+split QKV lo
__device__ float g_xp[T_SEQ * D_EMB];               // x  prepped (tf32+perm)
__device__ float g_yp[T_SEQ * D_EMB];               // y  prepped (tf32+perm)
__device__ float g_wqp[QKV_N * D_EMB];              // Wqkv prepped
__device__ float g_wop[D_EMB * D_EMB];              // Wout prepped

// ---------------------------------------------------------------------------
// helpers
// ---------------------------------------------------------------------------
__device__ __forceinline__ uint32_t smem_u32(const void* p) {
    uint32_t a;
    asm("{ .reg .u64 t; cvta.to.shared.u64 t, %1; cvt.u32.u64 %0, t; }"
        : "=r"(a) : "l"(p));
    return a;
}
__device__ __forceinline__ void cp_async16(uint32_t dst, const void* src) {
    asm volatile("cp.async.cg.shared.global [%0], [%1], 16;"
                 :: "r"(dst), "l"(src));
}
__device__ __forceinline__ void cp_commit() {
    asm volatile("cp.async.commit_group;");
}
template <int N>
__device__ __forceinline__ void cp_wait() {
    asm volatile("cp.async.wait_group %0;" :: "n"(N));
}
__device__ __forceinline__ void ldsm_x4(uint32_t* r, uint32_t addr) {
    asm volatile("ldmatrix.sync.aligned.m8n8.x4.shared.b16 {%0,%1,%2,%3}, [%4];"
                 : "=r"(r[0]), "=r"(r[1]), "=r"(r[2]), "=r"(r[3]) : "r"(addr));
}
__device__ __forceinline__ void ldsm_x4_t(uint32_t* r, uint32_t addr) {
    asm volatile(
        "ldmatrix.sync.aligned.m8n8.x4.trans.shared.b16 {%0,%1,%2,%3}, [%4];"
        : "=r"(r[0]), "=r"(r[1]), "=r"(r[2]), "=r"(r[3]) : "r"(addr));
}
__device__ __forceinline__ void mma_bf16(float* d, const uint32_t* a,
                                         uint32_t b0, uint32_t b1) {
    asm volatile(
        "mma.sync.aligned.m16n8k16.row.col.f32.bf16.bf16.f32 "
        "{%0,%1,%2,%3}, {%4,%5,%6,%7}, {%8,%9}, {%0,%1,%2,%3};"
        : "+f"(d[0]), "+f"(d[1]), "+f"(d[2]), "+f"(d[3])
        : "r"(a[0]), "r"(a[1]), "r"(a[2]), "r"(a[3]), "r"(b0), "r"(b1));
}
__device__ __forceinline__ void mma_tf32(float* d, const uint32_t* a,
                                         uint32_t b0, uint32_t b1) {
    asm volatile(
        "mma.sync.aligned.m16n8k8.row.col.f32.tf32.tf32.f32 "
        "{%0,%1,%2,%3}, {%4,%5,%6,%7}, {%8,%9}, {%0,%1,%2,%3};"
        : "+f"(d[0]), "+f"(d[1]), "+f"(d[2]), "+f"(d[3])
        : "r"(a[0]), "r"(a[1]), "r"(a[2]), "r"(a[3]), "r"(b0), "r"(b1));
}
__device__ __forceinline__ uint32_t cvt_tf32(float x) {
    uint32_t r;
    asm("cvt.rna.tf32.f32 %0, %1;" : "=r"(r) : "f"(x));
    return r;
}

// fast exp: 2^(x*log2e) via round+poly, FMA-only (no MUFU).
__device__ __forceinline__ float fexp(float x) {
    x = fmaxf(x, -88.0f);
    float t  = fmaf(x, 1.4426950408889634f, 12582912.0f);
    float nf = t - 12582912.0f;
    float r  = fmaf(x, 1.4426950408889634f, -nf);
    float p  = 1.3333558146428443e-3f;
    p = fmaf(p, r, 9.6181291076284772e-3f);
    p = fmaf(p, r, 5.5504108664821580e-2f);
    p = fmaf(p, r, 2.4022650695910072e-1f);
    p = fmaf(p, r, 6.9314718055994531e-1f);
    p = fmaf(p, r, 1.0f);
    int n = (int)nf;
    return p * __int_as_float((n + 127) << 23);
}

// split pair of fp32 -> packed bf16x2 hi and lo
__device__ __forceinline__ void split2(float a, float b,
                                       uint32_t& hi, uint32_t& lo) {
    __nv_bfloat16 ha = __float2bfloat16(a), hb = __float2bfloat16(b);
    float ra = a - __bfloat162float(ha);
    float rb = b - __bfloat162float(hb);
    __nv_bfloat162 H = __halves2bfloat162(ha, hb);
    __nv_bfloat162 L = __halves2bfloat162(__float2bfloat16(ra),
                                          __float2bfloat16(rb));
    hi = *(uint32_t*)&H;
    lo = *(uint32_t*)&L;
}

// ---------------------------------------------------------------------------
// Prep: fp32 -> tf32-rounded bits, K-columns permuted within each 8-group
// to order [0,4,1,5,2,6,3,7].
// ---------------------------------------------------------------------------
__global__ void prep_tf32_kernel(const float* __restrict__ in,
                                 float* __restrict__ out, int ngroups) {
    int gidx = blockIdx.x * blockDim.x + threadIdx.x;
    if (gidx >= ngroups) return;
    size_t base = (size_t)gidx * 8;
    float4 lo = *(const float4*)(in + base);
    float4 hi = *(const float4*)(in + base + 4);
    float4 o0, o1;
    o0.x = __uint_as_float(cvt_tf32(lo.x));
    o0.y = __uint_as_float(cvt_tf32(hi.x));
    o0.z = __uint_as_float(cvt_tf32(lo.y));
    o0.w = __uint_as_float(cvt_tf32(hi.y));
    o1.x = __uint_as_float(cvt_tf32(lo.z));
    o1.y = __uint_as_float(cvt_tf32(hi.z));
    o1.z = __uint_as_float(cvt_tf32(lo.w));
    o1.w = __uint_as_float(cvt_tf32(hi.w));
    *(float4*)(out + base) = o0;
    *(float4*)(out + base + 4) = o1;
}

// ---------------------------------------------------------------------------
// tf32 GEMM on prepped operands (Round 10/11 config — measured best).
// CTA 128x128, BK=32, 256 threads (2m x 4n warps, warp 64x32), 2 CTAs/SM,
// 2-stage cp.async. smem pitch 160B.
// ---------------------------------------------------------------------------
#define P2 160
#define A2 (128 * P2)                 // 20480 per tensor
#define S2 (2 * A2)                   // 40960 per stage
#define GEMM_SMEM (2 * S2)            // 81920

__device__ __forceinline__ void tf32_stage_load(
    uint32_t stg, const float* A, const float* B, int K, int k0, int tid)
{
#pragma unroll
    for (int i = 0; i < 8; i++) {
        int c = tid + i * 256;                 // 0..2047 16B chunks
        int sel = c >> 10;                     // 0=A, 1=B
        int rem = c & 1023;
        int row = rem >> 3, ch = rem & 7;
        const float* src = sel ? B : A;
        cp_async16(stg + sel * A2 + row * P2 + ch * 16,
                   src + (size_t)row * K + k0 + ch * 4);
    }
}

__global__ __launch_bounds__(256, 2) void gemm_tf32p(
    const float* __restrict__ A, const float* __restrict__ B,
    float* __restrict__ C, int M, int N, int K)
{
    extern __shared__ __align__(128) char sm[];
    const uint32_t sbase = smem_u32(sm);

    const int tid = threadIdx.x;
    const int wid = tid >> 5, lane = tid & 31;
    const int wm = wid >> 2, wn = wid & 3;         // 2m x 4n warps
    const int bm = blockIdx.x * 128, bn = blockIdx.y * 128;

    const float* Ab = A + (size_t)bm * K;
    const float* Bb = B + (size_t)bn * K;

    float acc[4][4][4];
#pragma unroll
    for (int mt = 0; mt < 4; mt++)
#pragma unroll
        for (int nt = 0; nt < 4; nt++)
#pragma unroll
            for (int q = 0; q < 4; q++) acc[mt][nt][q] = 0.0f;

    const int nkt = K >> 5;

    tf32_stage_load(sbase,      Ab, Bb, K, 0,  tid); cp_commit();
    tf32_stage_load(sbase + S2, Ab, Bb, K, 32, tid); cp_commit();

    const int g = lane >> 2, c = lane & 3;
    const int arow = wm * 64 + g;
    const int brow = wn * 32 + g;

    for (int kt = 0; kt < nkt; kt++) {
        cp_wait<1>();
        __syncthreads();
        const uint32_t stgo = (kt & 1) * S2;

#pragma unroll
        for (int ks = 0; ks < 4; ks++) {
            const int kb = ks * 32 + c * 8;        // byte offset of k-pair
            uint32_t bf[4][2];
#pragma unroll
            for (int nt = 0; nt < 4; nt++) {
                uint2 v = *(const uint2*)(sm + stgo + A2
                                          + (brow + nt * 8) * P2 + kb);
                bf[nt][0] = v.x;
                bf[nt][1] = v.y;
            }
            uint32_t af[4][4];
#pragma unroll
            for (int mt = 0; mt < 4; mt++) {
                uint32_t ad = stgo + (arow + mt * 16) * P2 + kb;
                uint2 v0 = *(const uint2*)(sm + ad);
                uint2 v1 = *(const uint2*)(sm + ad + 8 * P2);
                af[mt][0] = v0.x; af[mt][2] = v0.y;
                af[mt][1] = v1.x; af[mt][3] = v1.y;
            }
#pragma unroll
            for (int mt = 0; mt < 4; mt++)
#pragma unroll
                for (int nt = 0; nt < 4; nt++)
                    mma_tf32(acc[mt][nt], af[mt], bf[nt][0], bf[nt][1]);
        }

        __syncthreads();
        if (kt + 2 < nkt) {
            tf32_stage_load(sbase + stgo, Ab, Bb, K, (kt + 2) * 32, tid);
        }
        cp_commit();
    }

    // epilogue
    const int l4 = lane & 3;
#pragma unroll
    for (int mt = 0; mt < 4; mt++) {
        const int r0 = bm + wm * 64 + mt * 16 + g;
#pragma unroll
        for (int nt = 0; nt < 4; nt++) {
            const int col = bn + wn * 32 + nt * 8 + l4 * 2;
            *(float2*)(C + (size_t)r0 * N + col) =
                make_float2(acc[mt][nt][0], acc[mt][nt][1]);
            *(float2*)(C + (size_t)(r0 + 8) * N + col) =
                make_float2(acc[mt][nt][2], acc[mt][nt][3]);
        }
    }
}

// ---------------------------------------------------------------------------
// Fused RoPE + bf16 hi/lo split of the QKV tensor (unchanged, passing).
// ---------------------------------------------------------------------------
__global__ void rope_split_kernel(const float* __restrict__ cosp,
                                  const float* __restrict__ sinp)
{
    int idx = blockIdx.x * blockDim.x + threadIdx.x;
    const int total = T_SEQ * NG * 6 * 64;
    if (idx >= total) return;
    int i = idx & 63;
    int r = idx >> 6;
    int s = r % 6; r /= 6;
    int g = r & 7;
    int t = r >> 3;

    const size_t off = (size_t)t * QKV_N + g * 768 + s * 128;
    const float* base = g_qkv + off;
    const float sc = (s < 4) ? 0.08838834764831845f : 1.0f;

    int d1, d2;
    float o1, o2;
    if (s < 5 && i < 32) {
        float x1 = base[i], x2 = base[i + 32];
        float c1 = cosp[t * 64 + i],      s1 = sinp[t * 64 + i];
        float c2 = cosp[t * 64 + i + 32], s2 = sinp[t * 64 + i + 32];
        o1 = (x1 * c1 - x2 * s1) * sc;
        o2 = (x2 * c2 + x1 * s2) * sc;
        d1 = i; d2 = i + 32;
    } else if (s < 5) {
        d1 = i + 32; d2 = i + 64;
        o1 = base[d1] * sc; o2 = base[d2] * sc;
    } else {
        d1 = i; d2 = i + 64;
        o1 = base[d1]; o2 = base[d2];
    }
    __nv_bfloat16 h1 = __float2bfloat16(o1);
    __nv_bfloat16 h2 = __float2bfloat16(o2);
    g_qkvh[off + d1] = h1;
    g_qkvh[off + d2] = h2;
    g_qkvl[off + d1] = __float2bfloat16(o1 - __bfloat162float(h1));
    g_qkvl[off + d2] = __float2bfloat16(o2 - __bfloat162float(h2));
}

// ---------------------------------------------------------------------------
// Tensor-core flash attention (bf16x3, causal) — Round 11 config (passing).
// q-block 64, kv-tile 32, 128 threads (4 warps), 2 CTAs/SM.
// ---------------------------------------------------------------------------
#define AP   272
#define KVT  (32 * AP)               // 8704 per tensor tile
#define KVBUF (4 * KVT)              // 34816 (Kh,Kl,Vh,Vl)
#define ATTN_SMEM (2 * KVBUF)        // 69632

__device__ __forceinline__ void attn_load_kv(
    uint32_t dstbase, const __nv_bfloat16* kh, const __nv_bfloat16* kl,
    const __nv_bfloat16* vh, const __nv_bfloat16* vl, int k0, int tid)
{
    const __nv_bfloat16* srcs[4] = {kh, kl, vh, vl};
#pragma unroll
    for (int it = 0; it < 16; it++) {
        int c = tid + it * 128;            // 0..2047 16B chunks
        int tensor = c >> 9;               // 512 chunks per tensor (32x16)
        int rem = c & 511;
        int row = rem >> 4, ch = rem & 15;
        cp_async16(dstbase + tensor * KVT + row * AP + ch * 16,
                   srcs[tensor] + (size_t)(k0 + row) * QKV_N + ch * 8);
    }
}

__global__ __launch_bounds__(128, 2) void attn_mma_kernel()
{
    extern __shared__ __align__(128) char sma[];
    const uint32_t sbase = smem_u32(sma);
    const int tid = threadIdx.x;
    const int wid = tid >> 5, lane = tid & 31;

    const int qb = (gridDim.x - 1) - blockIdx.x;   // 64-row q block, heavy first
    const int h  = blockIdx.y;
    const int g = h >> 2, s = h & 3;

    const __nv_bfloat16* Qh = g_qkvh + (size_t)(qb * 64) * QKV_N
                            + g * 768 + s * 128;
    const __nv_bfloat16* Ql = g_qkvl + (size_t)(qb * 64) * QKV_N
                            + g * 768 + s * 128;
    const __nv_bfloat16* Kh = g_qkvh + g * 768 + 512;
    const __nv_bfloat16* Kl = g_qkvl + g * 768 + 512;
    const __nv_bfloat16* Vh = g_qkvh + g * 768 + 640;
    const __nv_bfloat16* Vl = g_qkvl + g * 768 + 640;

    // ---- stage Q (64 rows x 128 dims, hi+lo) into smem, then registers ----
#pragma unroll
    for (int it = 0; it < 16; it++) {
        int c = tid + it * 128;            // 0..2047 chunks
        int tensor = c >> 10;              // 1024 chunks per tensor (64x16)
        int rem = c & 1023;
        int row = rem >> 4, ch = rem & 15;
        const __nv_bfloat16* src = (tensor ? Ql : Qh);
        cp_async16(sbase + tensor * (64 * AP) + row * AP + ch * 16,
                   src + (size_t)row * QKV_N + ch * 8);
    }
    cp_commit();
    cp_wait<0>();
    __syncthreads();

    uint32_t qfh[8][4], qfl[8][4];
    {
        uint32_t qa = sbase + (wid * 16 + (lane & 15)) * AP + (lane >> 4) * 16;
#pragma unroll
        for (int ks = 0; ks < 8; ks++) {
            ldsm_x4(qfh[ks], qa + ks * 32);
            ldsm_x4(qfl[ks], qa + 64 * AP + ks * 32);
        }
    }
    __syncthreads();

    const int nt_tiles = 2 * qb + 2;       // kv tiles of 32 covering (qb+1)*64
    attn_load_kv(sbase, Kh, Kl, Vh, Vl, 0, tid);
    cp_commit();
    attn_load_kv(sbase + KVBUF, Kh, Kl, Vh, Vl, 32, tid);
    cp_commit();

    float oacc[16][4];
#pragma unroll
    for (int nt = 0; nt < 16; nt++)
#pragma unroll
        for (int q = 0; q < 4; q++) oacc[nt][q] = 0.0f;
    float m0 = -1e30f, m1 = -1e30f, l0 = 0.0f, l1 = 0.0f;

    const int row0 = qb * 64 + wid * 16 + (lane >> 2);
    const int row1 = row0 + 8;

    for (int kt = 0; kt < nt_tiles; kt++) {
        cp_wait<1>();
        __syncthreads();
        const uint32_t kb = sbase + (kt & 1) * KVBUF;
        const int k0 = kt * 32;

        // ---- S = Q K^T (bf16x3), S tile 16x32 per warp ----
        float sacc[4][4];
#pragma unroll
        for (int nt = 0; nt < 4; nt++)
#pragma unroll
            for (int q = 0; q < 4; q++) sacc[nt][q] = 0.0f;

        const uint32_t kaddr = kb + (lane & 15) * AP + (lane >> 4) * 16;
#pragma unroll
        for (int ks = 0; ks < 8; ks++) {
#pragma unroll
            for (int p = 0; p < 2; p++) {
                uint32_t kh4[4], kl4[4];
                uint32_t a = kaddr + p * 16 * AP + ks * 32;
                ldsm_x4(kh4, a);
                ldsm_x4(kl4, a + KVT);
                mma_bf16(sacc[2 * p],     qfh[ks], kh4[0], kh4[2]);
                mma_bf16(sacc[2 * p],     qfh[ks], kl4[0], kl4[2]);
                mma_bf16(sacc[2 * p],     qfl[ks], kh4[0], kh4[2]);
                mma_bf16(sacc[2 * p + 1], qfh[ks], kh4[1], kh4[3]);
                mma_bf16(sacc[2 * p + 1], qfh[ks], kl4[1], kl4[3]);
                mma_bf16(sacc[2 * p + 1], qfl[ks], kh4[1], kh4[3]);
            }
        }

        // ---- causal mask ----
        if (k0 + 31 > row0) {
#pragma unroll
            for (int nt = 0; nt < 4; nt++) {
                int col = k0 + nt * 8 + 2 * (lane & 3);
                if (col     > row0) sacc[nt][0] = -1e30f;
                if (col + 1 > row0) sacc[nt][1] = -1e30f;
                if (col     > row1) sacc[nt][2] = -1e30f;
                if (col + 1 > row1) sacc[nt][3] = -1e30f;
            }
        }

        // ---- online softmax ----
        float mt0 = -1e30f, mt1 = -1e30f;
#pragma unroll
        for (int nt = 0; nt < 4; nt++) {
            mt0 = fmaxf(mt0, fmaxf(sacc[nt][0], sacc[nt][1]));
            mt1 = fmaxf(mt1, fmaxf(sacc[nt][2], sacc[nt][3]));
        }
        mt0 = fmaxf(mt0, __shfl_xor_sync(0xffffffffu, mt0, 1));
        mt0 = fmaxf(mt0, __shfl_xor_sync(0xffffffffu, mt0, 2));
        mt1 = fmaxf(mt1, __shfl_xor_sync(0xffffffffu, mt1, 1));
        mt1 = fmaxf(mt1, __shfl_xor_sync(0xffffffffu, mt1, 2));

        float mn0 = fmaxf(m0, mt0), mn1 = fmaxf(m1, mt1);
        float c0 = fexp(m0 - mn0), c1 = fexp(m1 - mn1);
        m0 = mn0; m1 = mn1;

        float s0 = 0.0f, s1 = 0.0f;
#pragma unroll
        for (int nt = 0; nt < 4; nt++) {
            sacc[nt][0] = fexp(sacc[nt][0] - m0);
            sacc[nt][1] = fexp(sacc[nt][1] - m0);
            sacc[nt][2] = fexp(sacc[nt][2] - m1);
            sacc[nt][3] = fexp(sacc[nt][3] - m1);
            s0 += sacc[nt][0] + sacc[nt][1];
            s1 += sacc[nt][2] + sacc[nt][3];
        }
        s0 += __shfl_xor_sync(0xffffffffu, s0, 1);
        s0 += __shfl_xor_sync(0xffffffffu, s0, 2);
        s1 += __shfl_xor_sync(0xffffffffu, s1, 1);
        s1 += __shfl_xor_sync(0xffffffffu, s1, 2);
        l0 = l0 * c0 + s0;
        l1 = l1 * c1 + s1;
#pragma unroll
        for (int nt = 0; nt < 16; nt++) {
            oacc[nt][0] *= c0; oacc[nt][1] *= c0;
            oacc[nt][2] *= c1; oacc[nt][3] *= c1;
        }

        // ---- O += P V (bf16x3); P fragments from registers ----
        const uint32_t vbase = kb + 2 * KVT
            + ((lane & 7) + ((lane >> 3) & 1) * 8) * AP + (lane >> 4) * 16;
#pragma unroll
        for (int kk = 0; kk < 2; kk++) {
            uint32_t pah[4], pal[4];
            split2(sacc[2 * kk][0],     sacc[2 * kk][1],     pah[0], pal[0]);
            split2(sacc[2 * kk][2],     sacc[2 * kk][3],     pah[1], pal[1]);
            split2(sacc[2 * kk + 1][0], sacc[2 * kk + 1][1], pah[2], pal[2]);
            split2(sacc[2 * kk + 1][2], sacc[2 * kk + 1][3], pah[3], pal[3]);
#pragma unroll
            for (int nb = 0; nb < 8; nb++) {
                uint32_t vh4[4], vl4[4];
                uint32_t va = vbase + kk * 16 * AP + nb * 32;
                ldsm_x4_t(vh4, va);
                ldsm_x4_t(vl4, va + KVT);
                mma_bf16(oacc[2 * nb],     pah, vh4[0], vh4[1]);
                mma_bf16(oacc[2 * nb],     pah, vl4[0], vl4[1]);
                mma_bf16(oacc[2 * nb],     pal, vh4[0], vh4[1]);
                mma_bf16(oacc[2 * nb + 1], pah, vh4[2], vh4[3]);
                mma_bf16(oacc[2 * nb + 1], pah, vl4[2], vl4[3]);
                mma_bf16(oacc[2 * nb + 1], pal, vh4[2], vh4[3]);
            }
        }

        __syncthreads();
        if (kt + 2 < nt_tiles)
            attn_load_kv(sbase + (kt & 1) * KVBUF, Kh, Kl, Vh, Vl,
                         (kt + 2) * 32, tid);
        cp_commit();
    }

    // epilogue: y = O / l, tf32-rounded + column-permuted into g_yp.
    const float il0 = 1.0f / l0, il1 = 1.0f / l1;
    const int l4 = lane & 3;
    const int p1 = (l4 < 2) ? 4 * l4 : 4 * l4 - 7;
    const int p2 = (l4 < 2) ? 4 * l4 + 2 : 4 * l4 - 5;
#pragma unroll
    for (int nt = 0; nt < 16; nt++) {
        size_t b0 = (size_t)row0 * D_EMB + h * DH + nt * 8;
        size_t b1 = (size_t)row1 * D_EMB + h * DH + nt * 8;
        g_yp[b0 + p1] = __uint_as_float(cvt_tf32(oacc[nt][0] * il0));
        g_yp[b0 + p2] = __uint_as_float(cvt_tf32(oacc[nt][1] * il0));
        g_yp[b1 + p1] = __uint_as_float(cvt_tf32(oacc[nt][2] * il1));
        g_yp[b1 + p2] = __uint_as_float(cvt_tf32(oacc[nt][3] * il1));
    }
}

// ---------------------------------------------------------------------------
// kernel_launch — now with a capture-compatible stream fork so prep(Wout)
// (memory-bound) runs concurrently with gemm1+rope+attn (compute-bound).
// Stream/event objects are created once on the first (non-captured) call.
// ---------------------------------------------------------------------------
extern "C" void kernel_launch(void* const* d_in, const int* in_sizes, int n_in,
                              void* d_out, int out_size)
{
    const float* x    = (const float*)d_in[0];
    const float* Wqkv = (const float*)d_in[1];
    const float* Wout = (const float*)d_in[2];
    const float* cosp = (const float*)d_in[3];
    const float* sinp = (const float*)d_in[4];
    float* out = (float*)d_out;

    float *qkv, *xp, *yp, *wqp, *wop;
    cudaGetSymbolAddress((void**)&qkv, g_qkv);
    cudaGetSymbolAddress((void**)&xp,  g_xp);
    cudaGetSymbolAddress((void**)&yp,  g_yp);
    cudaGetSymbolAddress((void**)&wqp, g_wqp);
    cudaGetSymbolAddress((void**)&wop, g_wop);

    static cudaStream_t s2 = nullptr;
    static cudaEvent_t ev_fork = nullptr, ev_join = nullptr, ev_wq = nullptr;
    if (s2 == nullptr) {
        cudaStreamCreateWithFlags(&s2, cudaStreamNonBlocking);
        cudaEventCreateWithFlags(&ev_fork, cudaEventDisableTiming);
        cudaEventCreateWithFlags(&ev_join, cudaEventDisableTiming);
        cudaEventCreateWithFlags(&ev_wq,   cudaEventDisableTiming);
    }

    cudaFuncSetAttribute(gemm_tf32p,
                         cudaFuncAttributeMaxDynamicSharedMemorySize,
                         GEMM_SMEM);
    cudaFuncSetAttribute(attn_mma_kernel,
                         cudaFuncAttributeMaxDynamicSharedMemorySize,
                         ATTN_SMEM);

    // ---- fork: side stream handles Wqkv prep, then Wout prep ----
    cudaEventRecord(ev_fork, 0);
    cudaStreamWaitEvent(s2, ev_fork, 0);

    // side stream: prep Wqkv (needed by gemm1), then prep Wout (needed by
    // gemm2 only — overlaps gemm1 + rope + attention on the main stream)
    {
        int gq = (QKV_N * D_EMB) / 8;
        prep_tf32_kernel<<<(gq + 255) / 256, 256, 0, s2>>>(Wqkv, wqp, gq);
        cudaEventRecord(ev_wq, s2);
        int go = (D_EMB * D_EMB) / 8;
        prep_tf32_kernel<<<(go + 255) / 256, 256, 0, s2>>>(Wout, wop, go);
        cudaEventRecord(ev_join, s2);
    }

    // main stream: prep x (concurrent with Wqkv prep)
    {
        int gx = (T_SEQ * D_EMB) / 8;
        prep_tf32_kernel<<<(gx + 255) / 256, 256>>>(x, xp, gx);
    }
    // gemm1 needs Wqkv prepped
    cudaStreamWaitEvent(0, ev_wq, 0);

    // 2) QKV projection (tf32 tensor cores): qkv = x @ Wqkv^T
    gemm_tf32p<<<dim3(T_SEQ / 128, QKV_N / 128), 256, GEMM_SMEM>>>(
        xp, wqp, qkv, T_SEQ, QKV_N, D_EMB);
    // 3) fused RoPE + bf16 hi/lo split
    {
        int total = T_SEQ * NG * 6 * 64;
        rope_split_kernel<<<(total + 255) / 256, 256>>>(cosp, sinp);
    }
    // 4) tensor-core flash attention -> prepped y (g_yp)
    attn_mma_kernel<<<dim3(T_SEQ / 64, NH), 128, ATTN_SMEM>>>();

    // join: gemm2 needs Wout prepped (side stream)
    cudaStreamWaitEvent(0, ev_join, 0);
    // 5) output projection (tf32): out = y @ Wout^T
    gemm_tf32p<<<dim3(T_SEQ / 128, D_EMB / 128), 256, GEMM_SMEM>>>(
        yp, wop, out, T_SEQ, D_EMB, D_EMB);
}